// round 12
// baseline (speedup 1.0000x reference)
#include <cuda_runtime.h>

// Problem constants (fixed by the reference)
#define BB 8
#define NT 256
#define WHD 21
#define PP 441          // WHD*WHD
#define SPITCH 23       // padded patch pitch (23x23)
#define IMW 1024
#define ITERS 20
#define PTS 14          // points per lane: 32*14 = 448 >= 441
#define WIN 24          // staged f0 window (covers 21px span + bilinear + fp slack)

__global__ __launch_bounds__(32)
void mt_kernel(const float* __restrict__ track,
               const float* __restrict__ imgs,
               float* __restrict__ out)
{
    const int id = blockIdx.x;           // one warp per track
    const int b = id >> 8;               // id / NT (NT = 256)
    const int t = id & 255;

    const float* f0 = imgs + (size_t)b * 2 * IMW * IMW;   // frame 0 (H==W==1024)
    const float* f1 = f0 + (size_t)(IMW * IMW);           // frame 1

    __shared__ float sW[WIN * WIN];          // staged f0 window
    __shared__ float sP[SPITCH * SPITCH];    // zero-padded sampled patch

    const int lane = threadIdx.x & 31;       // bounded => p<PP folds for k<=12

    // per-lane shift state (uniform across the warp)
    float sx, sy;
    {
        const float SCALE = 21.0f / 1024.0f;   // exact in fp32
        sx = track[b * (NT * 2) + t * 2 + 0] / SCALE;
        sy = track[b * (NT * 2) + t * 2 + 1] / SCALE;
    }

    // zero the padded patch once; border stays zero forever
    #pragma unroll
    for (int k = lane; k < SPITCH * SPITCH; k += 32) sP[k] = 0.0f;

    // ---- hoisted per-k geometry (computed once, lives in registers) ----
    float gx[PTS], gy[PTS];
    int   pb[PTS];
    #pragma unroll
    for (int k = 0; k < PTS; ++k) {
        const int p = lane + k * 32;
        const int i = p / WHD;
        const int j = p - i * WHD;
        gx[k] = -1.0f + 0.1f * (float)j;
        gy[k] = -1.0f + 0.1f * (float)i;
        pb[k] = (i + 1) * SPITCH + (j + 1);
    }

    // direct-gather bilinear (exact reference clip-then-weight); used once for
    // f1 'second' and once for the final f0 sample
    auto bilinearG = [&](const float* __restrict__ f, float gxv, float gyv,
                         float ssx, float ssy) -> float {
        float x = (gxv + ssx) * 10.5f;   // WH*0.5
        float y = (gyv + ssy) * 10.5f;
        float fx = floorf(x);
        float fy = floorf(y);
        float x0 = fminf(fmaxf(fx,        0.0f), 1023.0f);
        float x1 = fminf(fmaxf(fx + 1.0f, 0.0f), 1023.0f);
        float y0 = fminf(fmaxf(fy,        0.0f), 1023.0f);
        float y1 = fminf(fmaxf(fy + 1.0f, 0.0f), 1023.0f);
        float wa = (y1 - y) * (x1 - x);
        float wb = (y1 - y) * (x  - x0);
        float wc = (y  - y0) * (x1 - x);
        float wd = (y  - y0) * (x  - x0);
        int xi0 = (int)x0, xi1 = (int)x1;
        const float* r0 = f + (int)y0 * IMW;
        const float* r1 = f + (int)y1 * IMW;
        return wa * __ldg(r0 + xi0) + wb * __ldg(r0 + xi1)
             + wc * __ldg(r1 + xi0) + wd * __ldg(r1 + xi1);
    };

    // 'second' (frame 1 at initial positions) — fixed for all iterations
    float second[PTS];
    {
        float* o1 = out + ((((size_t)b * 2) + 1) * NT + t) * PP;
        #pragma unroll
        for (int k = 0; k < PTS; ++k) {
            second[k] = 0.0f;
            if (k < PTS - 1 || lane < PP - 32 * (PTS - 1)) {   // p < PP (folds for k<13)
                second[k] = bilinearG(f1, gx[k], gy[k], sx, sy);
                o1[lane + k * 32] = second[k];
            }
        }
    }

    for (int it = 0; it < ITERS; ++it) {
        // ---- window base (uniform across warp; monotone indices => coverage) ----
        int cbase, rbase;
        {
            float xf = (-1.0f + sx) * 10.5f;   // x at j=0
            float yf = (-1.0f + sy) * 10.5f;   // y at i=0
            cbase = min(max((int)floorf(xf), 0), IMW - WIN);
            rbase = min(max((int)floorf(yf), 0), IMW - WIN);
        }

        // ---- stage 24x24 f0 window: 24 coalesced warp-LDGs ----
        if (lane < WIN) {
            const float* wsrc = f0 + rbase * IMW + cbase + lane;
            #pragma unroll
            for (int r = 0; r < WIN; ++r)
                sW[r * WIN + lane] = __ldg(wsrc + r * IMW);
        }
        __syncwarp();                          // window visible

        // ---- sample f0 from the window (exact clip-then-weight math) ----
        float o0[PTS];
        #pragma unroll
        for (int k = 0; k < PTS; ++k) {
            if (k < PTS - 1 || lane < PP - 32 * (PTS - 1)) {
                float x = (gx[k] + sx) * 10.5f;
                float y = (gy[k] + sy) * 10.5f;
                float fx = floorf(x);
                float fy = floorf(y);
                float x0 = fminf(fmaxf(fx,        0.0f), 1023.0f);
                float x1 = fminf(fmaxf(fx + 1.0f, 0.0f), 1023.0f);
                float y0 = fminf(fmaxf(fy,        0.0f), 1023.0f);
                float y1 = fminf(fmaxf(fy + 1.0f, 0.0f), 1023.0f);
                float wa = (y1 - y) * (x1 - x);
                float wb = (y1 - y) * (x  - x0);
                float wc = (y  - y0) * (x1 - x);
                float wd = (y  - y0) * (x  - x0);
                int xi0 = (int)x0 - cbase, xi1 = (int)x1 - cbase;
                const float* w0 = sW + ((int)y0 - rbase) * WIN;
                const float* w1 = sW + ((int)y1 - rbase) * WIN;
                o0[k] = wa * w0[xi0] + wb * w0[xi1]
                      + wc * w1[xi0] + wd * w1[xi1];
                sP[pb[k]] = o0[k];
            }
        }
        __syncwarp();                          // patch visible

        // ---- per-point zero-padded Sobel stencil + local accumulation ----
        float v0 = 0.f, v1 = 0.f, v2 = 0.f, v3 = 0.f, v4 = 0.f;
        #pragma unroll
        for (int k = 0; k < PTS; ++k) {
            if (k < PTS - 1 || lane < PP - 32 * (PTS - 1)) {
                const int pc = pb[k];
                float a00 = sP[pc - SPITCH - 1], a01 = sP[pc - SPITCH], a02 = sP[pc - SPITCH + 1];
                float a10 = sP[pc - 1],                                  a12 = sP[pc + 1];
                float a20 = sP[pc + SPITCH - 1], a21 = sP[pc + SPITCH], a22 = sP[pc + SPITCH + 1];
                float Ix = (a02 - a00) + 2.0f * (a12 - a10) + (a22 - a20);
                float Iy = (a20 - a00) + 2.0f * (a21 - a01) + (a22 - a02);
                float It = second[k] - o0[k];
                v0 = fmaf(Ix, Ix, v0);
                v1 = fmaf(Iy, Iy, v1);
                v2 = fmaf(Ix, Iy, v2);
                v3 = fmaf(Ix, It, v3);
                v4 = fmaf(Iy, It, v4);
            }
        }

        // ---- butterfly reduction: every lane ends with the full sums ----
        // (data dependency also orders all sP/sW reads before next iter's writes)
        #pragma unroll
        for (int off = 16; off; off >>= 1) {
            v0 += __shfl_xor_sync(0xffffffffu, v0, off);
            v1 += __shfl_xor_sync(0xffffffffu, v1, off);
            v2 += __shfl_xor_sync(0xffffffffu, v2, off);
            v3 += __shfl_xor_sync(0xffffffffu, v3, off);
            v4 += __shfl_xor_sync(0xffffffffu, v4, off);
        }

        // ---- 2x2 solve (every lane, identical) ----
        float det_inv = 1.0f / (v0 * v1 - v2 * v2);
        float Vx = det_inv * (v1    * (-v3) + (-v2) * (-v4));
        float Vy = det_inv * ((-v2) * (-v3) + v0    * (-v4));
        sx = sx - Vx;
        sy = sy - Vy;
    }

    // final sample of frame 0 at converged positions (direct gathers, once)
    {
        float* o0p = out + ((((size_t)b * 2) + 0) * NT + t) * PP;
        #pragma unroll
        for (int k = 0; k < PTS; ++k) {
            if (k < PTS - 1 || lane < PP - 32 * (PTS - 1)) {
                o0p[lane + k * 32] = bilinearG(f0, gx[k], gy[k], sx, sy);
            }
        }
    }
}

extern "C" void kernel_launch(void* const* d_in, const int* in_sizes, int n_in,
                              void* d_out, int out_size)
{
    // track_locs: 8*512 = 4096 floats; imgs: 8*2*1024*1024 floats.
    const float* track;
    const float* imgs;
    if (in_sizes[0] < in_sizes[1]) {
        track = (const float*)d_in[0];
        imgs  = (const float*)d_in[1];
    } else {
        track = (const float*)d_in[1];
        imgs  = (const float*)d_in[0];
    }
    float* out = (float*)d_out;
    mt_kernel<<<BB * NT, 32>>>(track, imgs, out);
}

// round 13
// speedup vs baseline: 1.0520x; 1.0520x over previous
#include <cuda_runtime.h>

// Problem constants (fixed by the reference)
#define BB 8
#define NT 256
#define WHD 21
#define PP 441          // WHD*WHD
#define PAD 23          // zero-padded patch dim
#define IMW 1024
#define ITERS 20
#define PTS 14          // points per lane: 32*14 = 448 >= 441

__global__ __launch_bounds__(32)
void mt_kernel(const float* __restrict__ track,
               const float* __restrict__ imgs,
               float* __restrict__ out)
{
    const int id = blockIdx.x;           // one warp per track
    const int b = id >> 8;               // id / NT (NT = 256)
    const int t = id & 255;

    const float* f0 = imgs + (size_t)b * 2 * IMW * IMW;   // frame 0 (H==W==1024)
    const float* f1 = f0 + (size_t)(IMW * IMW);           // frame 1

    __shared__ float sP[PAD * PAD];      // zero-padded sampled patch (warp-private)

    const int lane = threadIdx.x & 31;   // bounded -> guards fold for k<13

    // per-lane shift state (uniform across the warp)
    float sx, sy;
    {
        const float SCALE = 21.0f / 1024.0f;   // exact in fp32
        sx = track[b * (NT * 2) + t * 2 + 0] / SCALE;
        sy = track[b * (NT * 2) + t * 2 + 1] / SCALE;
    }

    // zero the padded patch once; border stays zero forever
    #pragma unroll
    for (int k = lane; k < PAD * PAD; k += 32) sP[k] = 0.0f;

    // ---- hoisted per-k geometry (computed once) ----
    float gx[PTS], gy[PTS];
    int   pb[PTS];
    #pragma unroll
    for (int k = 0; k < PTS; ++k) {
        const int p = lane + k * 32;
        const int i = p / WHD;
        const int j = p - i * WHD;
        gx[k] = -1.0f + 0.1f * (float)j;
        gy[k] = -1.0f + 0.1f * (float)i;
        pb[k] = (i + 1) * PAD + (j + 1);
    }

    // general bilinear (exact reference clip-then-weight)
    auto bilinearG = [&](const float* __restrict__ f, float gxv, float gyv,
                         float ssx, float ssy) -> float {
        float x = (gxv + ssx) * 10.5f;   // WH*0.5
        float y = (gyv + ssy) * 10.5f;
        float fx = floorf(x);
        float fy = floorf(y);
        float x0 = fminf(fmaxf(fx,        0.0f), 1023.0f);
        float x1 = fminf(fmaxf(fx + 1.0f, 0.0f), 1023.0f);
        float y0 = fminf(fmaxf(fy,        0.0f), 1023.0f);
        float y1 = fminf(fmaxf(fy + 1.0f, 0.0f), 1023.0f);
        float wa = (y1 - y) * (x1 - x);
        float wb = (y1 - y) * (x  - x0);
        float wc = (y  - y0) * (x1 - x);
        float wd = (y  - y0) * (x  - x0);
        int xi0 = (int)x0, xi1 = (int)x1;
        const float* r0 = f + (int)y0 * IMW;
        const float* r1 = f + (int)y1 * IMW;
        return wa * __ldg(r0 + xi0) + wb * __ldg(r0 + xi1)
             + wc * __ldg(r1 + xi0) + wd * __ldg(r1 + xi1);
    };

    // 'second' (frame 1 at initial positions) — fixed for all iterations
    float second[PTS];
    {
        float* o1 = out + ((((size_t)b * 2) + 1) * NT + t) * PP;
        #pragma unroll
        for (int k = 0; k < PTS; ++k) {
            second[k] = 0.0f;
            if (k < PTS - 1 || lane < PP - 32 * (PTS - 1)) {   // p < PP
                second[k] = bilinearG(f1, gx[k], gy[k], sx, sy);
                o1[lane + k * 32] = second[k];
            }
        }
    }

    for (int it = 0; it < ITERS; ++it) {
        // ---- warp-uniform interior test (sx, sy uniform across lanes) ----
        bool interior;
        {
            float xlo = (-1.0f + sx) * 10.5f, xhi = (1.0f + sx) * 10.5f;
            float ylo = (-1.0f + sy) * 10.5f, yhi = (1.0f + sy) * 10.5f;
            interior = (floorf(xlo) >= 0.0f) && (floorf(xhi) + 1.0f <= 1023.0f)
                    && (floorf(ylo) >= 0.0f) && (floorf(yhi) + 1.0f <= 1023.0f);
        }

        // ---- sample f0 (lane-consecutive points -> coalesced L1 gathers) ----
        float o0[PTS];
        if (interior) {
            // clamp-free: bit-identical to general path when indices in-range
            #pragma unroll
            for (int k = 0; k < PTS; ++k) {
                if (k < PTS - 1 || lane < PP - 32 * (PTS - 1)) {
                    float x  = (gx[k] + sx) * 10.5f;
                    float y  = (gy[k] + sy) * 10.5f;
                    float fx = floorf(x);
                    float fy = floorf(y);
                    float x1 = fx + 1.0f;
                    float y1 = fy + 1.0f;
                    float dx1 = x1 - x,  dx0 = x - fx;   // (x1-x), (x-x0)
                    float dy1 = y1 - y,  dy0 = y - fy;   // (y1-y), (y-y0)
                    const float* base = f0 + (int)fy * IMW + (int)fx;
                    o0[k] = (dy1 * dx1) * __ldg(base)
                          + (dy1 * dx0) * __ldg(base + 1)
                          + (dy0 * dx1) * __ldg(base + IMW)
                          + (dy0 * dx0) * __ldg(base + IMW + 1);
                    sP[pb[k]] = o0[k];
                }
            }
        } else {
            #pragma unroll
            for (int k = 0; k < PTS; ++k) {
                if (k < PTS - 1 || lane < PP - 32 * (PTS - 1)) {
                    o0[k] = bilinearG(f0, gx[k], gy[k], sx, sy);
                    sP[pb[k]] = o0[k];
                }
            }
        }
        __syncwarp();                    // patch writes visible to stencil reads

        // ---- per-point zero-padded Sobel stencil + local accumulation ----
        float v0 = 0.f, v1 = 0.f, v2 = 0.f, v3 = 0.f, v4 = 0.f;
        #pragma unroll
        for (int k = 0; k < PTS; ++k) {
            if (k < PTS - 1 || lane < PP - 32 * (PTS - 1)) {
                const int pc = pb[k];
                float a00 = sP[pc - PAD - 1], a01 = sP[pc - PAD], a02 = sP[pc - PAD + 1];
                float a10 = sP[pc - 1],                            a12 = sP[pc + 1];
                float a20 = sP[pc + PAD - 1], a21 = sP[pc + PAD], a22 = sP[pc + PAD + 1];
                float Ix = (a02 - a00) + 2.0f * (a12 - a10) + (a22 - a20);
                float Iy = (a20 - a00) + 2.0f * (a21 - a01) + (a22 - a02);
                float It = second[k] - o0[k];
                v0 = fmaf(Ix, Ix, v0);
                v1 = fmaf(Iy, Iy, v1);
                v2 = fmaf(Ix, Iy, v2);
                v3 = fmaf(Ix, It, v3);
                v4 = fmaf(Iy, It, v4);
            }
        }

        // ---- butterfly reduction: every lane ends with the full sums ----
        #pragma unroll
        for (int off = 16; off; off >>= 1) {
            v0 += __shfl_xor_sync(0xffffffffu, v0, off);
            v1 += __shfl_xor_sync(0xffffffffu, v1, off);
            v2 += __shfl_xor_sync(0xffffffffu, v2, off);
            v3 += __shfl_xor_sync(0xffffffffu, v3, off);
            v4 += __shfl_xor_sync(0xffffffffu, v4, off);
        }

        // ---- 2x2 solve (every lane, identical) ----
        float det_inv = 1.0f / (v0 * v1 - v2 * v2);
        float Vx = det_inv * (v1    * (-v3) + (-v2) * (-v4));
        float Vy = det_inv * ((-v2) * (-v3) + v0    * (-v4));
        sx = sx - Vx;
        sy = sy - Vy;
    }

    // final sample of frame 0 at converged positions (general path, once)
    {
        float* o0p = out + ((((size_t)b * 2) + 0) * NT + t) * PP;
        #pragma unroll
        for (int k = 0; k < PTS; ++k) {
            if (k < PTS - 1 || lane < PP - 32 * (PTS - 1)) {
                o0p[lane + k * 32] = bilinearG(f0, gx[k], gy[k], sx, sy);
            }
        }
    }
}

extern "C" void kernel_launch(void* const* d_in, const int* in_sizes, int n_in,
                              void* d_out, int out_size)
{
    // track_locs: 8*512 = 4096 floats; imgs: 8*2*1024*1024 floats.
    const float* track;
    const float* imgs;
    if (in_sizes[0] < in_sizes[1]) {
        track = (const float*)d_in[0];
        imgs  = (const float*)d_in[1];
    } else {
        track = (const float*)d_in[1];
        imgs  = (const float*)d_in[0];
    }
    float* out = (float*)d_out;
    mt_kernel<<<BB * NT, 32>>>(track, imgs, out);
}

// round 14
// speedup vs baseline: 1.0588x; 1.0065x over previous
#include <cuda_runtime.h>

// Problem constants (fixed by the reference)
#define BB 8
#define NT 256
#define WHD 21
#define PP 441          // WHD*WHD
#define PAD 23          // zero-padded patch dim
#define IMW 1024
#define ITERS 20
#define PTS 14          // points per lane: 32*14 = 448 >= 441

__global__ __launch_bounds__(32)
void mt_kernel(const float* __restrict__ track,
               const float* __restrict__ imgs,
               float* __restrict__ out)
{
    const int id = blockIdx.x;           // one warp per track
    const int b = id >> 8;               // id / NT (NT = 256)
    const int t = id & 255;

    const float* f0 = imgs + (size_t)b * 2 * IMW * IMW;   // frame 0 (H==W==1024)
    const float* f1 = f0 + (size_t)(IMW * IMW);           // frame 1

    __shared__ float sP[PAD * PAD];      // zero-padded sampled patch (warp-private)

    const int lane = threadIdx.x & 31;   // bounded -> guards fold for k<13

    // per-lane shift state (uniform across the warp)
    float sx, sy;
    {
        const float SCALE = 21.0f / 1024.0f;   // exact in fp32
        sx = track[b * (NT * 2) + t * 2 + 0] / SCALE;
        sy = track[b * (NT * 2) + t * 2 + 1] / SCALE;
    }

    // zero the padded patch once; border stays zero forever
    #pragma unroll
    for (int k = lane; k < PAD * PAD; k += 32) sP[k] = 0.0f;

    // ---- hoisted per-k geometry (computed once) ----
    float gx[PTS], gy[PTS];      // exact grid coords (general path)
    float gxs[PTS], gys[PTS];    // pre-scaled by 10.5 (interior fast path)
    int   pb[PTS];
    #pragma unroll
    for (int k = 0; k < PTS; ++k) {
        const int p = lane + k * 32;
        const int i = p / WHD;
        const int j = p - i * WHD;
        gx[k] = -1.0f + 0.1f * (float)j;
        gy[k] = -1.0f + 0.1f * (float)i;
        gxs[k] = gx[k] * 10.5f;
        gys[k] = gy[k] * 10.5f;
        pb[k] = (i + 1) * PAD + (j + 1);
    }

    // general bilinear (exact reference clip-then-weight)
    auto bilinearG = [&](const float* __restrict__ f, float gxv, float gyv,
                         float ssx, float ssy) -> float {
        float x = (gxv + ssx) * 10.5f;   // WH*0.5
        float y = (gyv + ssy) * 10.5f;
        float fx = floorf(x);
        float fy = floorf(y);
        float x0 = fminf(fmaxf(fx,        0.0f), 1023.0f);
        float x1 = fminf(fmaxf(fx + 1.0f, 0.0f), 1023.0f);
        float y0 = fminf(fmaxf(fy,        0.0f), 1023.0f);
        float y1 = fminf(fmaxf(fy + 1.0f, 0.0f), 1023.0f);
        float wa = (y1 - y) * (x1 - x);
        float wb = (y1 - y) * (x  - x0);
        float wc = (y  - y0) * (x1 - x);
        float wd = (y  - y0) * (x  - x0);
        int xi0 = (int)x0, xi1 = (int)x1;
        const float* r0 = f + (int)y0 * IMW;
        const float* r1 = f + (int)y1 * IMW;
        return wa * __ldg(r0 + xi0) + wb * __ldg(r0 + xi1)
             + wc * __ldg(r1 + xi0) + wd * __ldg(r1 + xi1);
    };

    // 'second' (frame 1 at initial positions) — fixed for all iterations
    float second[PTS];
    {
        float* o1 = out + ((((size_t)b * 2) + 1) * NT + t) * PP;
        #pragma unroll
        for (int k = 0; k < PTS; ++k) {
            second[k] = 0.0f;
            if (k < PTS - 1 || lane < PP - 32 * (PTS - 1)) {   // p < PP
                second[k] = bilinearG(f1, gx[k], gy[k], sx, sy);
                o1[lane + k * 32] = second[k];
            }
        }
    }

    for (int it = 0; it < ITERS; ++it) {
        // ---- warp-uniform interior test with 1-px safety margin ----
        bool interior;
        {
            float xlo = (-1.0f + sx) * 10.5f, xhi = (1.0f + sx) * 10.5f;
            float ylo = (-1.0f + sy) * 10.5f, yhi = (1.0f + sy) * 10.5f;
            interior = (floorf(xlo) >= 1.0f) && (floorf(xhi) + 2.0f <= 1023.0f)
                    && (floorf(ylo) >= 1.0f) && (floorf(yhi) + 2.0f <= 1023.0f);
        }

        // ---- sample f0 (lane-consecutive points -> coalesced L1 gathers) ----
        float o0[PTS];
        if (interior) {
            const float sxs = sx * 10.5f;
            const float sys = sy * 10.5f;
            #pragma unroll
            for (int k = 0; k < PTS; ++k) {
                if (k < PTS - 1 || lane < PP - 32 * (PTS - 1)) {
                    float x  = gxs[k] + sxs;
                    float y  = gys[k] + sys;
                    float fx = floorf(x);
                    float fy = floorf(y);
                    float dx0 = x - fx;             // exact
                    float dy0 = y - fy;             // exact
                    float dx1 = (fx + 1.0f) - x;    // == x1 - x, exact ops
                    float dy1 = (fy + 1.0f) - y;
                    int idx = (int)fmaf(fy, 1024.0f, fx);   // exact (< 2^20)
                    const float* base = f0 + idx;
                    o0[k] = (dy1 * dx1) * __ldg(base)
                          + (dy1 * dx0) * __ldg(base + 1)
                          + (dy0 * dx1) * __ldg(base + IMW)
                          + (dy0 * dx0) * __ldg(base + IMW + 1);
                    sP[pb[k]] = o0[k];
                }
            }
        } else {
            #pragma unroll
            for (int k = 0; k < PTS; ++k) {
                if (k < PTS - 1 || lane < PP - 32 * (PTS - 1)) {
                    o0[k] = bilinearG(f0, gx[k], gy[k], sx, sy);
                    sP[pb[k]] = o0[k];
                }
            }
        }
        __syncwarp();                    // patch writes visible to stencil reads

        // ---- per-point zero-padded Sobel stencil + local accumulation ----
        float v0 = 0.f, v1 = 0.f, v2 = 0.f, v3 = 0.f, v4 = 0.f;
        #pragma unroll
        for (int k = 0; k < PTS; ++k) {
            if (k < PTS - 1 || lane < PP - 32 * (PTS - 1)) {
                const int pc = pb[k];
                float a00 = sP[pc - PAD - 1], a01 = sP[pc - PAD], a02 = sP[pc - PAD + 1];
                float a10 = sP[pc - 1],                            a12 = sP[pc + 1];
                float a20 = sP[pc + PAD - 1], a21 = sP[pc + PAD], a22 = sP[pc + PAD + 1];
                float Ix = (a02 - a00) + 2.0f * (a12 - a10) + (a22 - a20);
                float Iy = (a20 - a00) + 2.0f * (a21 - a01) + (a22 - a02);
                float It = second[k] - o0[k];
                v0 = fmaf(Ix, Ix, v0);
                v1 = fmaf(Iy, Iy, v1);
                v2 = fmaf(Ix, Iy, v2);
                v3 = fmaf(Ix, It, v3);
                v4 = fmaf(Iy, It, v4);
            }
        }

        // ---- butterfly reduction: every lane ends with the full sums ----
        #pragma unroll
        for (int off = 16; off; off >>= 1) {
            v0 += __shfl_xor_sync(0xffffffffu, v0, off);
            v1 += __shfl_xor_sync(0xffffffffu, v1, off);
            v2 += __shfl_xor_sync(0xffffffffu, v2, off);
            v3 += __shfl_xor_sync(0xffffffffu, v3, off);
            v4 += __shfl_xor_sync(0xffffffffu, v4, off);
        }

        // ---- 2x2 solve (every lane, identical) ----
        float det_inv = 1.0f / (v0 * v1 - v2 * v2);
        float Vx = det_inv * (v1    * (-v3) + (-v2) * (-v4));
        float Vy = det_inv * ((-v2) * (-v3) + v0    * (-v4));
        sx = sx - Vx;
        sy = sy - Vy;
    }

    // final sample of frame 0 at converged positions (exact general path)
    {
        float* o0p = out + ((((size_t)b * 2) + 0) * NT + t) * PP;
        #pragma unroll
        for (int k = 0; k < PTS; ++k) {
            if (k < PTS - 1 || lane < PP - 32 * (PTS - 1)) {
                o0p[lane + k * 32] = bilinearG(f0, gx[k], gy[k], sx, sy);
            }
        }
    }
}

extern "C" void kernel_launch(void* const* d_in, const int* in_sizes, int n_in,
                              void* d_out, int out_size)
{
    // track_locs: 8*512 = 4096 floats; imgs: 8*2*1024*1024 floats.
    const float* track;
    const float* imgs;
    if (in_sizes[0] < in_sizes[1]) {
        track = (const float*)d_in[0];
        imgs  = (const float*)d_in[1];
    } else {
        track = (const float*)d_in[1];
        imgs  = (const float*)d_in[0];
    }
    float* out = (float*)d_out;
    mt_kernel<<<BB * NT, 32>>>(track, imgs, out);
}